// round 10
// baseline (speedup 1.0000x reference)
#include <cuda_runtime.h>
#include <math.h>

#define BB 16
#define SS 1024
#define DM 512
#define HH 8
#define DKK 64
#define BH (BB*HH)

// ---------------- scratch (device globals: no allocations allowed) ----------
__device__ float g_cq[(size_t)BB*SS*DM];
__device__ float g_ck[(size_t)BB*SS*DM];
__device__ float g_cv[(size_t)BB*SS*DM];
__device__ float g_Q [(size_t)BB*SS*DM];
__device__ float g_K [(size_t)BB*SS*DM];
__device__ float g_V [(size_t)BB*SS*DM];
__device__ float g_ctx[(size_t)BB*SS*DM];
__device__ float g_fc [(size_t)BB*SS*DM];
__device__ float g_rowsum[(size_t)BH*SS];
__device__ float g_attn_fb[(size_t)BH*SS*SS];   // fallback if attn not in d_out

// ---------------- tf32 helpers ----------------------------------------------
__device__ __forceinline__ float tf32r(float f) {
    unsigned u; asm("cvt.rna.tf32.f32 %0, %1;" : "=r"(u) : "f"(f));
    return __uint_as_float(u);
}
__device__ __forceinline__ void mma_tf32(float* c, const unsigned* a, const unsigned* b) {
    asm volatile("mma.sync.aligned.m16n8k8.row.col.f32.tf32.tf32.f32 "
        "{%0,%1,%2,%3}, {%4,%5,%6,%7}, {%8,%9}, {%0,%1,%2,%3};"
        : "+f"(c[0]), "+f"(c[1]), "+f"(c[2]), "+f"(c[3])
        : "r"(a[0]), "r"(a[1]), "r"(a[2]), "r"(a[3]), "r"(b[0]), "r"(b[1]));
}

// ---------------- 3x3 conv, 1 channel, pad 1, over (S, F) ------------------
__global__ void conv3x3_kernel(const float* __restrict__ x,
                               const float* __restrict__ w,
                               const float* __restrict__ bias,
                               float* __restrict__ y) {
    int bs = blockIdx.x;
    int b = bs >> 10;
    int s = bs & (SS - 1);
    int f = threadIdx.x;                // 0..511
    __shared__ float rows[3][DM + 2];
    #pragma unroll
    for (int r = 0; r < 3; r++) {
        int ss = s + r - 1;
        rows[r][f + 1] = (ss >= 0 && ss < SS) ? x[((size_t)b*SS + ss)*DM + f] : 0.f;
    }
    if (f < 3) { rows[f][0] = 0.f; rows[f][DM + 1] = 0.f; }
    __syncthreads();
    float acc = bias[0];
    #pragma unroll
    for (int r = 0; r < 3; r++)
        #pragma unroll
        for (int c = 0; c < 3; c++)
            acc += rows[r][f + c] * w[r*3 + c];
    y[((size_t)b*SS + s)*DM + f] = acc;
}

// ===== tf32 GEMM: C[M,512] = A[M,512] x B[512,512], block 128x128 ==========
#define PA 36
#define PB 136
__global__ void __launch_bounds__(256)
gemm512_tf32(const float* __restrict__ A, const float* __restrict__ B,
             float* __restrict__ C) {
    __shared__ __align__(16) float As[128 * PA];
    __shared__ __align__(16) float Bs[32 * PB];
    const int tid = threadIdx.x;
    const int warp = tid >> 5, lane = tid & 31;
    const int g = lane >> 2, tig = lane & 3;
    const int warpM = warp >> 2, warpN = warp & 3;
    const int rowC = blockIdx.y * 128, colC = blockIdx.x * 128;
    float acc[4][4][4] = {};
    const int ar = tid >> 3, ac4 = (tid & 7) * 4;
    const int br = tid >> 5, bc4 = (tid & 31) * 4;
    for (int kt = 0; kt < 512; kt += 32) {
        #pragma unroll
        for (int i = 0; i < 4; i++) {
            int r = ar + i*32;
            float4 v = *(const float4*)(A + (size_t)(rowC + r)*512 + kt + ac4);
            float* d = As + r*PA + ac4;
            d[0]=tf32r(v.x); d[1]=tf32r(v.y); d[2]=tf32r(v.z); d[3]=tf32r(v.w);
        }
        #pragma unroll
        for (int i = 0; i < 4; i++) {
            int r = br + i*8;
            float4 v = *(const float4*)(B + (size_t)(kt + r)*512 + colC + bc4);
            float* d = Bs + r*PB + bc4;
            d[0]=tf32r(v.x); d[1]=tf32r(v.y); d[2]=tf32r(v.z); d[3]=tf32r(v.w);
        }
        __syncthreads();
        #pragma unroll
        for (int kk = 0; kk < 4; kk++) {
            unsigned af[4][4], bf[4][2];
            #pragma unroll
            for (int mt = 0; mt < 4; mt++) {
                const float* p = As + (warpM*64 + mt*16 + g)*PA + kk*8 + tig;
                af[mt][0] = __float_as_uint(p[0]);
                af[mt][1] = __float_as_uint(p[8*PA]);
                af[mt][2] = __float_as_uint(p[4]);
                af[mt][3] = __float_as_uint(p[8*PA + 4]);
            }
            #pragma unroll
            for (int nt = 0; nt < 4; nt++) {
                const float* p = Bs + (kk*8 + tig)*PB + warpN*32 + nt*8 + g;
                bf[nt][0] = __float_as_uint(p[0]);
                bf[nt][1] = __float_as_uint(p[4*PB]);
            }
            #pragma unroll
            for (int mt = 0; mt < 4; mt++)
                #pragma unroll
                for (int nt = 0; nt < 4; nt++)
                    mma_tf32(acc[mt][nt], af[mt], bf[nt]);
        }
        __syncthreads();
    }
    #pragma unroll
    for (int mt = 0; mt < 4; mt++) {
        int r0 = rowC + warpM*64 + mt*16 + g;
        #pragma unroll
        for (int nt = 0; nt < 4; nt++) {
            int c = colC + warpN*32 + nt*8 + tig*2;
            *(float2*)(C + (size_t)r0*512 + c)     = make_float2(acc[mt][nt][0], acc[mt][nt][1]);
            *(float2*)(C + (size_t)(r0+8)*512 + c) = make_float2(acc[mt][nt][2], acc[mt][nt][3]);
        }
    }
}

// ===== pass 1: per-row sum of exp(scaled masked scores), no attn traffic ====
// grid (8 rowtiles, BH); CTA: 128 q-rows x all 1024 k-cols (8 tiles)
#define PQ 72
__global__ void __launch_bounds__(256)
rowsum_tf32(const float* __restrict__ Q, const float* __restrict__ Kk,
            const unsigned char* __restrict__ mask, float* __restrict__ rowsum) {
    extern __shared__ float sm1[];
    float* As = sm1;                  // 128*PQ  (Q tile)
    float* Bs = sm1 + 128*PQ;         // 128*PQ  (K tile, n-major)
    float* rows_s = sm1 + 2*128*PQ;   // 4*128
    const int z = blockIdx.y, b = z >> 3, h = z & 7;
    const float* Ab = Q  + (size_t)b*SS*DM + h*DKK;
    const float* Bb = Kk + (size_t)b*SS*DM + h*DKK;
    const int tid = threadIdx.x, warp = tid >> 5, lane = tid & 31;
    const int g = lane >> 2, tig = lane & 3;
    const int warpM = warp >> 2, warpN = warp & 3;
    const int rowC = blockIdx.x * 128;
    // load Q tile (128x64) once
    #pragma unroll
    for (int i = 0; i < 8; i++) {
        int lin = tid + i*256;
        int r = lin >> 4, c4 = (lin & 15) * 4;
        float4 v = *(const float4*)(Ab + (size_t)(rowC + r)*DM + c4);
        float* d = As + r*PQ + c4;
        d[0]=tf32r(v.x); d[1]=tf32r(v.y); d[2]=tf32r(v.z); d[3]=tf32r(v.w);
    }
    float suml[8] = {0.f,0.f,0.f,0.f,0.f,0.f,0.f,0.f};
    const unsigned char* mrow = mask + (size_t)b*SS*SS;
    for (int ct = 0; ct < 8; ct++) {
        const int colC = ct*128;
        __syncthreads();                       // prev mma done reading Bs
        #pragma unroll
        for (int i = 0; i < 8; i++) {
            int lin = tid + i*256;
            int r = lin >> 4, c4 = (lin & 15) * 4;
            float4 v = *(const float4*)(Bb + (size_t)(colC + r)*DM + c4);
            float* d = Bs + r*PQ + c4;
            d[0]=tf32r(v.x); d[1]=tf32r(v.y); d[2]=tf32r(v.z); d[3]=tf32r(v.w);
        }
        __syncthreads();
        float acc[4][4][4] = {};
        #pragma unroll
        for (int kk = 0; kk < 8; kk++) {
            unsigned af[4][4], bf[4][2];
            #pragma unroll
            for (int mt = 0; mt < 4; mt++) {
                const float* p = As + (warpM*64 + mt*16 + g)*PQ + kk*8 + tig;
                af[mt][0] = __float_as_uint(p[0]);
                af[mt][1] = __float_as_uint(p[8*PQ]);
                af[mt][2] = __float_as_uint(p[4]);
                af[mt][3] = __float_as_uint(p[8*PQ + 4]);
            }
            #pragma unroll
            for (int nt = 0; nt < 4; nt++) {
                const float* p = Bs + (warpN*32 + nt*8 + g)*PQ + kk*8 + tig;
                bf[nt][0] = __float_as_uint(p[0]);
                bf[nt][1] = __float_as_uint(p[4]);
            }
            #pragma unroll
            for (int mt = 0; mt < 4; mt++)
                #pragma unroll
                for (int nt = 0; nt < 4; nt++)
                    mma_tf32(acc[mt][nt], af[mt], bf[nt]);
        }
        #pragma unroll
        for (int mt = 0; mt < 4; mt++) {
            int r0 = rowC + warpM*64 + mt*16 + g;
            #pragma unroll
            for (int nt = 0; nt < 4; nt++) {
                int c = colC + warpN*32 + nt*8 + tig*2;
                #pragma unroll
                for (int rr = 0; rr < 2; rr++) {
                    uchar2 m2 = *(const uchar2*)(mrow + (size_t)(r0 + rr*8)*SS + c);
                    float e0 = m2.x ? 0.f : __expf(acc[mt][nt][rr*2+0] * 0.125f);
                    float e1 = m2.y ? 0.f : __expf(acc[mt][nt][rr*2+1] * 0.125f);
                    suml[mt*2+rr] += e0 + e1;
                }
            }
        }
    }
    // reduce across tig lanes (deterministic)
    #pragma unroll
    for (int j = 0; j < 8; j++) {
        float v = suml[j];
        v += __shfl_xor_sync(0xffffffffu, v, 1);
        v += __shfl_xor_sync(0xffffffffu, v, 2);
        suml[j] = v;
    }
    if (tig == 0) {
        #pragma unroll
        for (int j = 0; j < 8; j++) {
            int rl = warpM*64 + (j>>1)*16 + g + (j&1)*8;
            rows_s[warpN*128 + rl] = suml[j];
        }
    }
    __syncthreads();
    if (tid < 128)
        rowsum[(size_t)z*SS + rowC + tid] =
            rows_s[tid] + rows_s[128+tid] + rows_s[256+tid] + rows_s[384+tid];
}

// ===== pass 2: recompute scores, write normalized attn, accumulate context ==
// grid (8 rowtiles, BH); CTA: 128 q-rows x all cols; ctx[128x64] in regs
#define PP 132
__global__ void __launch_bounds__(256)
attn_fused_tf32(const float* __restrict__ Q, const float* __restrict__ Kk,
                const float* __restrict__ V, const unsigned char* __restrict__ mask,
                const float* __restrict__ rowsum,
                float* __restrict__ attn, float* __restrict__ ctx) {
    extern __shared__ float sm2[];
    float* As  = sm2;                 // 128*PQ  (Q tile)
    float* KVs = sm2 + 128*PQ;        // 128*PQ  (K tile n-major, then V tile k-major)
    float* Ps  = sm2 + 2*128*PQ;      // 128*PP  (normalized P tile)
    const int z = blockIdx.y, b = z >> 3, h = z & 7;
    const float* Ab = Q  + (size_t)b*SS*DM + h*DKK;
    const float* Bb = Kk + (size_t)b*SS*DM + h*DKK;
    const float* Vb = V  + (size_t)b*SS*DM + h*DKK;
    const int tid = threadIdx.x, warp = tid >> 5, lane = tid & 31;
    const int g = lane >> 2, tig = lane & 3;
    const int warpM = warp >> 2, warpN = warp & 3;
    const int rowC = blockIdx.x * 128;
    // load Q tile
    #pragma unroll
    for (int i = 0; i < 8; i++) {
        int lin = tid + i*256;
        int r = lin >> 4, c4 = (lin & 15) * 4;
        float4 v = *(const float4*)(Ab + (size_t)(rowC + r)*DM + c4);
        float* d = As + r*PQ + c4;
        d[0]=tf32r(v.x); d[1]=tf32r(v.y); d[2]=tf32r(v.z); d[3]=tf32r(v.w);
    }
    // per-row inverse sums
    float inv[8];
    #pragma unroll
    for (int j = 0; j < 8; j++) {
        int row = rowC + warpM*64 + (j>>1)*16 + g + (j&1)*8;
        inv[j] = 1.0f / rowsum[(size_t)z*SS + row];
    }
    float cacc[4][2][4] = {};
    float* attn_z = attn + (size_t)z*SS*SS;
    const unsigned char* mrow = mask + (size_t)b*SS*SS;
    for (int ct = 0; ct < 8; ct++) {
        const int colC = ct*128;
        __syncthreads();                       // prev ctx mma done (KVs, Ps free)
        #pragma unroll
        for (int i = 0; i < 8; i++) {          // K tile -> KVs (n-major)
            int lin = tid + i*256;
            int r = lin >> 4, c4 = (lin & 15) * 4;
            float4 v = *(const float4*)(Bb + (size_t)(colC + r)*DM + c4);
            float* d = KVs + r*PQ + c4;
            d[0]=tf32r(v.x); d[1]=tf32r(v.y); d[2]=tf32r(v.z); d[3]=tf32r(v.w);
        }
        __syncthreads();
        float acc[4][4][4] = {};
        #pragma unroll
        for (int kk = 0; kk < 8; kk++) {       // scores mma
            unsigned af[4][4], bf[4][2];
            #pragma unroll
            for (int mt = 0; mt < 4; mt++) {
                const float* p = As + (warpM*64 + mt*16 + g)*PQ + kk*8 + tig;
                af[mt][0] = __float_as_uint(p[0]);
                af[mt][1] = __float_as_uint(p[8*PQ]);
                af[mt][2] = __float_as_uint(p[4]);
                af[mt][3] = __float_as_uint(p[8*PQ + 4]);
            }
            #pragma unroll
            for (int nt = 0; nt < 4; nt++) {
                const float* p = KVs + (warpN*32 + nt*8 + g)*PQ + kk*8 + tig;
                bf[nt][0] = __float_as_uint(p[0]);
                bf[nt][1] = __float_as_uint(p[4]);
            }
            #pragma unroll
            for (int mt = 0; mt < 4; mt++)
                #pragma unroll
                for (int nt = 0; nt < 4; nt++)
                    mma_tf32(acc[mt][nt], af[mt], bf[nt]);
        }
        __syncthreads();                       // scores mma done reading KVs
        #pragma unroll
        for (int i = 0; i < 2; i++) {          // V tile -> KVs (k-major, 128x64)
            int lin = tid + i*256;
            int r = lin >> 4, c4 = (lin & 15) * 4;
            float4 v = *(const float4*)(Vb + (size_t)(colC + r)*DM + c4);
            float* d = KVs + r*PQ + c4;
            d[0]=tf32r(v.x); d[1]=tf32r(v.y); d[2]=tf32r(v.z); d[3]=tf32r(v.w);
        }
        // P = exp(scale*s) (masked), normalized; write attn + stage to Ps
        #pragma unroll
        for (int mt = 0; mt < 4; mt++) {
            int rl = warpM*64 + mt*16 + g;
            #pragma unroll
            for (int nt = 0; nt < 4; nt++) {
                int cl = warpN*32 + nt*8 + tig*2;
                #pragma unroll
                for (int rr = 0; rr < 2; rr++) {
                    size_t gbase = (size_t)(rowC + rl + rr*8)*SS + colC + cl;
                    uchar2 m2 = *(const uchar2*)(mrow + gbase);
                    float e0 = m2.x ? 0.f : __expf(acc[mt][nt][rr*2+0] * 0.125f);
                    float e1 = m2.y ? 0.f : __expf(acc[mt][nt][rr*2+1] * 0.125f);
                    float s = inv[mt*2+rr];
                    float2 pn = make_float2(tf32r(e0*s), tf32r(e1*s));
                    *(float2*)(attn_z + gbase) = make_float2(e0*s, e1*s);
                    *(float2*)(Ps + (rl + rr*8)*PP + cl) = pn;
                }
            }
        }
        __syncthreads();                       // Ps + V ready
        #pragma unroll
        for (int kk = 0; kk < 16; kk++) {      // ctx mma: k=128 per tile
            unsigned af[4][4], bf[2][2];
            #pragma unroll
            for (int mt = 0; mt < 4; mt++) {
                const float* p = Ps + (warpM*64 + mt*16 + g)*PP + kk*8 + tig;
                af[mt][0] = __float_as_uint(p[0]);
                af[mt][1] = __float_as_uint(p[8*PP]);
                af[mt][2] = __float_as_uint(p[4]);
                af[mt][3] = __float_as_uint(p[8*PP + 4]);
            }
            #pragma unroll
            for (int nt = 0; nt < 2; nt++) {
                const float* p = KVs + (kk*8 + tig)*PQ + warpN*16 + nt*8 + g;
                bf[nt][0] = __float_as_uint(p[0]);
                bf[nt][1] = __float_as_uint(p[4*PQ]);
            }
            #pragma unroll
            for (int mt = 0; mt < 4; mt++)
                #pragma unroll
                for (int nt = 0; nt < 2; nt++)
                    mma_tf32(cacc[mt][nt], af[mt], bf[nt]);
        }
    }
    // write ctx (already normalized)
    #pragma unroll
    for (int mt = 0; mt < 4; mt++) {
        int r0 = b*SS + rowC + warpM*64 + mt*16 + g;
        #pragma unroll
        for (int nt = 0; nt < 2; nt++) {
            int c = h*DKK + warpN*16 + nt*8 + tig*2;
            *(float2*)(ctx + (size_t)r0*DM + c)     = make_float2(cacc[mt][nt][0], cacc[mt][nt][1]);
            *(float2*)(ctx + (size_t)(r0+8)*DM + c) = make_float2(cacc[mt][nt][2], cacc[mt][nt][3]);
        }
    }
}

// -------- fused residual add + LayerNorm(512), eps=1e-5, no affine ----------
__global__ void ln_kernel(const float* __restrict__ fc,
                          const float* __restrict__ resid,
                          float* __restrict__ out) {
    const size_t row = blockIdx.x;
    const int tid = threadIdx.x;
    const int lane = tid & 31, warp = tid >> 5;
    float4 a = *(const float4*)(fc + row*DM + tid*4);
    float4 r = *(const float4*)(resid + row*DM + tid*4);
    float x0 = a.x + r.x, x1 = a.y + r.y, x2 = a.z + r.z, x3 = a.w + r.w;
    float s  = x0 + x1 + x2 + x3;
    float sq = x0*x0 + x1*x1 + x2*x2 + x3*x3;
    #pragma unroll
    for (int o = 16; o; o >>= 1) {
        s  += __shfl_xor_sync(0xffffffffu, s,  o);
        sq += __shfl_xor_sync(0xffffffffu, sq, o);
    }
    __shared__ float s1[4], s2[4];
    if (lane == 0) { s1[warp] = s; s2[warp] = sq; }
    __syncthreads();
    s  = s1[0] + s1[1] + s1[2] + s1[3];
    sq = s2[0] + s2[1] + s2[2] + s2[3];
    float mu  = s * (1.0f / DM);
    float var = sq * (1.0f / DM) - mu * mu;
    float rstd = rsqrtf(var + 1e-5f);
    float4 o4;
    o4.x = (x0 - mu) * rstd; o4.y = (x1 - mu) * rstd;
    o4.z = (x2 - mu) * rstd; o4.w = (x3 - mu) * rstd;
    *(float4*)(out + row*DM + tid*4) = o4;
}

// ---------------------------------------------------------------------------
extern "C" void kernel_launch(void* const* d_in, const int* in_sizes, int n_in,
                              void* d_out, int out_size) {
    const float* inQ = (const float*)d_in[0];
    const float* inK = (const float*)d_in[1];
    const float* inV = (const float*)d_in[2];
    const unsigned char* mask = (const unsigned char*)d_in[3];
    const float* cwq = (const float*)d_in[4];  const float* cbq = (const float*)d_in[5];
    const float* cwk = (const float*)d_in[6];  const float* cbk = (const float*)d_in[7];
    const float* cwv = (const float*)d_in[8];  const float* cbv = (const float*)d_in[9];
    const float* WQ = (const float*)d_in[10];
    const float* WK = (const float*)d_in[11];
    const float* WV = (const float*)d_in[12];
    const float* FC = (const float*)d_in[13];
    float* out = (float*)d_out;

    float *cq, *ck, *cv, *Q, *K, *V, *ctx, *fco, *attn_fb, *rowsum;
    cudaGetSymbolAddress((void**)&cq, g_cq);
    cudaGetSymbolAddress((void**)&ck, g_ck);
    cudaGetSymbolAddress((void**)&cv, g_cv);
    cudaGetSymbolAddress((void**)&Q,  g_Q);
    cudaGetSymbolAddress((void**)&K,  g_K);
    cudaGetSymbolAddress((void**)&V,  g_V);
    cudaGetSymbolAddress((void**)&ctx, g_ctx);
    cudaGetSymbolAddress((void**)&fco, g_fc);
    cudaGetSymbolAddress((void**)&attn_fb, g_attn_fb);
    cudaGetSymbolAddress((void**)&rowsum, g_rowsum);

    const size_t BSD  = (size_t)BB * SS * DM;
    const size_t BHSS = (size_t)BH * SS * SS;
    float* attn = ((size_t)out_size >= BSD + BHSS) ? (out + BSD) : attn_fb;

    const int SM1 = (2*128*PQ + 4*128) * 4;             // 75776 B
    const int SM2 = (2*128*PQ + 128*PP) * 4;            // 141312 B
    cudaFuncSetAttribute(rowsum_tf32,     cudaFuncAttributeMaxDynamicSharedMemorySize, SM1);
    cudaFuncSetAttribute(attn_fused_tf32, cudaFuncAttributeMaxDynamicSharedMemorySize, SM2);

    conv3x3_kernel<<<BB*SS, DM>>>(inQ, cwq, cbq, cq);
    conv3x3_kernel<<<BB*SS, DM>>>(inK, cwk, cbk, ck);
    conv3x3_kernel<<<BB*SS, DM>>>(inV, cwv, cbv, cv);

    dim3 gp(4, (BB*SS)/128);
    gemm512_tf32<<<gp, 256>>>(cq, WQ, Q);
    gemm512_tf32<<<gp, 256>>>(ck, WK, K);
    gemm512_tf32<<<gp, 256>>>(cv, WV, V);

    rowsum_tf32<<<dim3(8, BH), 256, SM1>>>(Q, K, mask, rowsum);
    attn_fused_tf32<<<dim3(8, BH), 256, SM2>>>(Q, K, V, mask, rowsum, attn, ctx);

    gemm512_tf32<<<gp, 256>>>(ctx, FC, fco);
    ln_kernel<<<BB*SS, 128>>>(fco, inQ, out);
}

// round 12
// speedup vs baseline: 1.0859x; 1.0859x over previous
#include <cuda_runtime.h>
#include <math.h>

#define BB 16
#define SS 1024
#define DM 512
#define HH 8
#define DKK 64
#define BH (BB*HH)

// ---------------- scratch (device globals: no allocations allowed) ----------
__device__ float g_cq[(size_t)BB*SS*DM];
__device__ float g_ck[(size_t)BB*SS*DM];
__device__ float g_cv[(size_t)BB*SS*DM];
__device__ float g_Q [(size_t)BB*SS*DM];
__device__ float g_K [(size_t)BB*SS*DM];
__device__ float g_V [(size_t)BB*SS*DM];
__device__ float g_ctx[(size_t)BB*SS*DM];
__device__ float g_fc [(size_t)BB*SS*DM];
__device__ float g_attn_fb[(size_t)BH*SS*SS];   // fallback if attn not in d_out

// ---------------- tf32 helpers ----------------------------------------------
__device__ __forceinline__ float tf32r(float f) {
    unsigned u; asm("cvt.rna.tf32.f32 %0, %1;" : "=r"(u) : "f"(f));
    return __uint_as_float(u);
}
__device__ __forceinline__ void mma_tf32(float* c, const unsigned* a, const unsigned* b) {
    asm volatile("mma.sync.aligned.m16n8k8.row.col.f32.tf32.tf32.f32 "
        "{%0,%1,%2,%3}, {%4,%5,%6,%7}, {%8,%9}, {%0,%1,%2,%3};"
        : "+f"(c[0]), "+f"(c[1]), "+f"(c[2]), "+f"(c[3])
        : "r"(a[0]), "r"(a[1]), "r"(a[2]), "r"(a[3]), "r"(b[0]), "r"(b[1]));
}

// ---------------- 3x3 conv, 1 channel, pad 1, over (S, F) ------------------
__global__ void conv3x3_kernel(const float* __restrict__ x,
                               const float* __restrict__ w,
                               const float* __restrict__ bias,
                               float* __restrict__ y) {
    int bs = blockIdx.x;
    int b = bs >> 10;
    int s = bs & (SS - 1);
    int f = threadIdx.x;                // 0..511
    __shared__ float rows[3][DM + 2];
    #pragma unroll
    for (int r = 0; r < 3; r++) {
        int ss = s + r - 1;
        rows[r][f + 1] = (ss >= 0 && ss < SS) ? x[((size_t)b*SS + ss)*DM + f] : 0.f;
    }
    if (f < 3) { rows[f][0] = 0.f; rows[f][DM + 1] = 0.f; }
    __syncthreads();
    float acc = bias[0];
    #pragma unroll
    for (int r = 0; r < 3; r++)
        #pragma unroll
        for (int c = 0; c < 3; c++)
            acc += rows[r][f + c] * w[r*3 + c];
    y[((size_t)b*SS + s)*DM + f] = acc;
}

// ===== tf32 GEMM with register-prefetch pipeline ============================
// C[M,512] = A[M,512] x B[512,512], block 128x128, BK=32
#define PA 36
#define PB 136
__global__ void __launch_bounds__(256)
gemm512_tf32(const float* __restrict__ A, const float* __restrict__ B,
             float* __restrict__ C) {
    __shared__ __align__(16) float As[128 * PA];
    __shared__ __align__(16) float Bs[32 * PB];
    const int tid = threadIdx.x;
    const int warp = tid >> 5, lane = tid & 31;
    const int g = lane >> 2, tig = lane & 3;
    const int warpM = warp >> 2, warpN = warp & 3;
    const int rowC = blockIdx.y * 128, colC = blockIdx.x * 128;
    float acc[4][4][4] = {};
    const int ar = tid >> 3, ac4 = (tid & 7) * 4;
    const int br = tid >> 5, bc4 = (tid & 31) * 4;
    float4 pva[4], pvb[4];
    #pragma unroll
    for (int i = 0; i < 4; i++)
        pva[i] = *(const float4*)(A + (size_t)(rowC + ar + i*32)*512 + ac4);
    #pragma unroll
    for (int i = 0; i < 4; i++)
        pvb[i] = *(const float4*)(B + (size_t)(br + i*8)*512 + colC + bc4);
    for (int kt = 0; kt < 512; kt += 32) {
        #pragma unroll
        for (int i = 0; i < 4; i++) {
            float* d = As + (ar + i*32)*PA + ac4;
            d[0]=tf32r(pva[i].x); d[1]=tf32r(pva[i].y);
            d[2]=tf32r(pva[i].z); d[3]=tf32r(pva[i].w);
        }
        #pragma unroll
        for (int i = 0; i < 4; i++) {
            float* d = Bs + (br + i*8)*PB + bc4;
            d[0]=tf32r(pvb[i].x); d[1]=tf32r(pvb[i].y);
            d[2]=tf32r(pvb[i].z); d[3]=tf32r(pvb[i].w);
        }
        __syncthreads();
        if (kt + 32 < 512) {            // prefetch next tile while mma runs
            #pragma unroll
            for (int i = 0; i < 4; i++)
                pva[i] = *(const float4*)(A + (size_t)(rowC + ar + i*32)*512 + kt + 32 + ac4);
            #pragma unroll
            for (int i = 0; i < 4; i++)
                pvb[i] = *(const float4*)(B + (size_t)(kt + 32 + br + i*8)*512 + colC + bc4);
        }
        #pragma unroll
        for (int kk = 0; kk < 4; kk++) {
            unsigned af[4][4], bf[4][2];
            #pragma unroll
            for (int mt = 0; mt < 4; mt++) {
                const float* p = As + (warpM*64 + mt*16 + g)*PA + kk*8 + tig;
                af[mt][0] = __float_as_uint(p[0]);
                af[mt][1] = __float_as_uint(p[8*PA]);
                af[mt][2] = __float_as_uint(p[4]);
                af[mt][3] = __float_as_uint(p[8*PA + 4]);
            }
            #pragma unroll
            for (int nt = 0; nt < 4; nt++) {
                const float* p = Bs + (kk*8 + tig)*PB + warpN*32 + nt*8 + g;
                bf[nt][0] = __float_as_uint(p[0]);
                bf[nt][1] = __float_as_uint(p[4*PB]);
            }
            #pragma unroll
            for (int mt = 0; mt < 4; mt++)
                #pragma unroll
                for (int nt = 0; nt < 4; nt++)
                    mma_tf32(acc[mt][nt], af[mt], bf[nt]);
        }
        __syncthreads();
    }
    #pragma unroll
    for (int mt = 0; mt < 4; mt++) {
        int r0 = rowC + warpM*64 + mt*16 + g;
        #pragma unroll
        for (int nt = 0; nt < 4; nt++) {
            int c = colC + warpN*32 + nt*8 + tig*2;
            *(float2*)(C + (size_t)r0*512 + c)     = make_float2(acc[mt][nt][0], acc[mt][nt][1]);
            *(float2*)(C + (size_t)(r0+8)*512 + c) = make_float2(acc[mt][nt][2], acc[mt][nt][3]);
        }
    }
}

// ===== scores tf32: per (b,h) C[1024,1024] = Q[1024,64] K[1024,64]^T ========
__global__ void __launch_bounds__(256)
scores_tf32(const float* __restrict__ Q, const float* __restrict__ Kk,
            const unsigned char* __restrict__ mask, float* __restrict__ attn) {
    __shared__ __align__(16) float As[128 * PA];
    __shared__ __align__(16) float Bs[128 * PA];
    const int z = blockIdx.z, b = z >> 3, h = z & 7;
    const float* Ab = Q  + (size_t)b*SS*DM + h*DKK;
    const float* Bb = Kk + (size_t)b*SS*DM + h*DKK;
    const int tid = threadIdx.x;
    const int warp = tid >> 5, lane = tid & 31;
    const int g = lane >> 2, tig = lane & 3;
    const int warpM = warp >> 2, warpN = warp & 3;
    const int rowC = blockIdx.y * 128, colC = blockIdx.x * 128;
    float acc[4][4][4] = {};
    const int ar = tid >> 3, ac4 = (tid & 7) * 4;
    for (int kt = 0; kt < DKK; kt += 32) {
        #pragma unroll
        for (int i = 0; i < 4; i++) {
            int r = ar + i*32;
            float4 v = *(const float4*)(Ab + (size_t)(rowC + r)*DM + kt + ac4);
            float* d = As + r*PA + ac4;
            d[0]=tf32r(v.x); d[1]=tf32r(v.y); d[2]=tf32r(v.z); d[3]=tf32r(v.w);
            float4 u = *(const float4*)(Bb + (size_t)(colC + r)*DM + kt + ac4);
            float* e = Bs + r*PA + ac4;
            e[0]=tf32r(u.x); e[1]=tf32r(u.y); e[2]=tf32r(u.z); e[3]=tf32r(u.w);
        }
        __syncthreads();
        #pragma unroll
        for (int kk = 0; kk < 4; kk++) {
            unsigned af[4][4], bf[4][2];
            #pragma unroll
            for (int mt = 0; mt < 4; mt++) {
                const float* p = As + (warpM*64 + mt*16 + g)*PA + kk*8 + tig;
                af[mt][0] = __float_as_uint(p[0]);
                af[mt][1] = __float_as_uint(p[8*PA]);
                af[mt][2] = __float_as_uint(p[4]);
                af[mt][3] = __float_as_uint(p[8*PA + 4]);
            }
            #pragma unroll
            for (int nt = 0; nt < 4; nt++) {
                const float* p = Bs + (warpN*32 + nt*8 + g)*PA + kk*8 + tig;
                bf[nt][0] = __float_as_uint(p[0]);
                bf[nt][1] = __float_as_uint(p[4]);
            }
            #pragma unroll
            for (int mt = 0; mt < 4; mt++)
                #pragma unroll
                for (int nt = 0; nt < 4; nt++)
                    mma_tf32(acc[mt][nt], af[mt], bf[nt]);
        }
        __syncthreads();
    }
    const float scale = 0.125f;
    const unsigned char* mrow = mask + (size_t)b*SS*SS;
    float* out = attn + (size_t)z*SS*SS;
    #pragma unroll
    for (int mt = 0; mt < 4; mt++) {
        int r0 = rowC + warpM*64 + mt*16 + g;
        #pragma unroll
        for (int nt = 0; nt < 4; nt++) {
            int c = colC + warpN*32 + nt*8 + tig*2;
            #pragma unroll
            for (int rr = 0; rr < 2; rr++) {
                size_t base = (size_t)(r0 + rr*8)*SS + c;
                uchar2 m2 = *(const uchar2*)(mrow + base);
                float2 v;
                v.x = m2.x ? -1e9f : acc[mt][nt][rr*2+0] * scale;
                v.y = m2.y ? -1e9f : acc[mt][nt][rr*2+1] * scale;
                *(float2*)(out + base) = v;
            }
        }
    }
}

// ===== context tf32: per (b,h) C[1024,64] = P[1024,1024] V[1024,64] ========
#define PV 72
__global__ void __launch_bounds__(256)
context_tf32(const float* __restrict__ attn, const float* __restrict__ V,
             float* __restrict__ ctx) {
    __shared__ __align__(16) float As[128 * PA];
    __shared__ __align__(16) float Bs[32 * PV];
    const int z = blockIdx.y, b = z >> 3, h = z & 7;
    const float* Ab = attn + (size_t)z*SS*SS;
    const float* Bb = V + (size_t)b*SS*DM + h*DKK;
    const int tid = threadIdx.x;
    const int warp = tid >> 5, lane = tid & 31;
    const int g = lane >> 2, tig = lane & 3;
    const int warpM = warp >> 1, warpN = warp & 1;
    const int rowC = blockIdx.x * 128;
    float acc[2][4][4] = {};
    const int ar = tid >> 3, ac4 = (tid & 7) * 4;
    const int vr = tid >> 4, vc4 = (tid & 15) * 4;
    for (int kt = 0; kt < SS; kt += 32) {
        #pragma unroll
        for (int i = 0; i < 4; i++) {
            int r = ar + i*32;
            float4 v = *(const float4*)(Ab + (size_t)(rowC + r)*SS + kt + ac4);
            float* d = As + r*PA + ac4;
            d[0]=tf32r(v.x); d[1]=tf32r(v.y); d[2]=tf32r(v.z); d[3]=tf32r(v.w);
        }
        #pragma unroll
        for (int i = 0; i < 2; i++) {
            int r = vr + i*16;
            float4 v = *(const float4*)(Bb + (size_t)(kt + r)*DM + vc4);
            float* d = Bs + r*PV + vc4;
            d[0]=tf32r(v.x); d[1]=tf32r(v.y); d[2]=tf32r(v.z); d[3]=tf32r(v.w);
        }
        __syncthreads();
        #pragma unroll
        for (int kk = 0; kk < 4; kk++) {
            unsigned af[2][4], bf[4][2];
            #pragma unroll
            for (int mt = 0; mt < 2; mt++) {
                const float* p = As + (warpM*32 + mt*16 + g)*PA + kk*8 + tig;
                af[mt][0] = __float_as_uint(p[0]);
                af[mt][1] = __float_as_uint(p[8*PA]);
                af[mt][2] = __float_as_uint(p[4]);
                af[mt][3] = __float_as_uint(p[8*PA + 4]);
            }
            #pragma unroll
            for (int nt = 0; nt < 4; nt++) {
                const float* p = Bs + (kk*8 + tig)*PV + warpN*32 + nt*8 + g;
                bf[nt][0] = __float_as_uint(p[0]);
                bf[nt][1] = __float_as_uint(p[4*PV]);
            }
            #pragma unroll
            for (int mt = 0; mt < 2; mt++)
                #pragma unroll
                for (int nt = 0; nt < 4; nt++)
                    mma_tf32(acc[mt][nt], af[mt], bf[nt]);
        }
        __syncthreads();
    }
    #pragma unroll
    for (int mt = 0; mt < 2; mt++) {
        int r0 = b*SS + rowC + warpM*32 + mt*16 + g;
        #pragma unroll
        for (int nt = 0; nt < 4; nt++) {
            int c = h*DKK + warpN*32 + nt*8 + tig*2;
            *(float2*)(ctx + (size_t)r0*DM + c)     = make_float2(acc[mt][nt][0], acc[mt][nt][1]);
            *(float2*)(ctx + (size_t)(r0+8)*DM + c) = make_float2(acc[mt][nt][2], acc[mt][nt][3]);
        }
    }
}

// -------- in-place row softmax, processed in REVERSE order for L2 reuse -----
__global__ void softmax_kernel(float* __restrict__ attn) {
    const size_t rowrev = (size_t)(BH*SS - 1) - blockIdx.x;   // reverse: hit L2-hot tail
    float* p = attn + rowrev * SS;
    const int tid = threadIdx.x;         // 128, 8 elems each
    const int lane = tid & 31, warp = tid >> 5;
    float4 v0 = *(float4*)(p + tid*8);
    float4 v1 = *(float4*)(p + tid*8 + 4);
    float m = fmaxf(fmaxf(fmaxf(v0.x, v0.y), fmaxf(v0.z, v0.w)),
                    fmaxf(fmaxf(v1.x, v1.y), fmaxf(v1.z, v1.w)));
    #pragma unroll
    for (int o = 16; o; o >>= 1) m = fmaxf(m, __shfl_xor_sync(0xffffffffu, m, o));
    __shared__ float sred[4];
    if (lane == 0) sred[warp] = m;
    __syncthreads();
    m = fmaxf(fmaxf(sred[0], sred[1]), fmaxf(sred[2], sred[3]));
    v0.x = __expf(v0.x - m); v0.y = __expf(v0.y - m);
    v0.z = __expf(v0.z - m); v0.w = __expf(v0.w - m);
    v1.x = __expf(v1.x - m); v1.y = __expf(v1.y - m);
    v1.z = __expf(v1.z - m); v1.w = __expf(v1.w - m);
    float s = v0.x + v0.y + v0.z + v0.w + v1.x + v1.y + v1.z + v1.w;
    #pragma unroll
    for (int o = 16; o; o >>= 1) s += __shfl_xor_sync(0xffffffffu, s, o);
    __syncthreads();
    if (lane == 0) sred[warp] = s;
    __syncthreads();
    s = sred[0] + sred[1] + sred[2] + sred[3];
    float inv = 1.0f / s;
    v0.x *= inv; v0.y *= inv; v0.z *= inv; v0.w *= inv;
    v1.x *= inv; v1.y *= inv; v1.z *= inv; v1.w *= inv;
    *(float4*)(p + tid*8)     = v0;
    *(float4*)(p + tid*8 + 4) = v1;
}

// -------- fused residual add + LayerNorm(512), eps=1e-5, no affine ----------
__global__ void ln_kernel(const float* __restrict__ fc,
                          const float* __restrict__ resid,
                          float* __restrict__ out) {
    const size_t row = blockIdx.x;
    const int tid = threadIdx.x;
    const int lane = tid & 31, warp = tid >> 5;
    float4 a = *(const float4*)(fc + row*DM + tid*4);
    float4 r = *(const float4*)(resid + row*DM + tid*4);
    float x0 = a.x + r.x, x1 = a.y + r.y, x2 = a.z + r.z, x3 = a.w + r.w;
    float s  = x0 + x1 + x2 + x3;
    float sq = x0*x0 + x1*x1 + x2*x2 + x3*x3;
    #pragma unroll
    for (int o = 16; o; o >>= 1) {
        s  += __shfl_xor_sync(0xffffffffu, s,  o);
        sq += __shfl_xor_sync(0xffffffffu, sq, o);
    }
    __shared__ float s1[4], s2[4];
    if (lane == 0) { s1[warp] = s; s2[warp] = sq; }
    __syncthreads();
    s  = s1[0] + s1[1] + s1[2] + s1[3];
    sq = s2[0] + s2[1] + s2[2] + s2[3];
    float mu  = s * (1.0f / DM);
    float var = sq * (1.0f / DM) - mu * mu;
    float rstd = rsqrtf(var + 1e-5f);
    float4 o4;
    o4.x = (x0 - mu) * rstd; o4.y = (x1 - mu) * rstd;
    o4.z = (x2 - mu) * rstd; o4.w = (x3 - mu) * rstd;
    *(float4*)(out + row*DM + tid*4) = o4;
}

// ---------------------------------------------------------------------------
extern "C" void kernel_launch(void* const* d_in, const int* in_sizes, int n_in,
                              void* d_out, int out_size) {
    const float* inQ = (const float*)d_in[0];
    const float* inK = (const float*)d_in[1];
    const float* inV = (const float*)d_in[2];
    const unsigned char* mask = (const unsigned char*)d_in[3];
    const float* cwq = (const float*)d_in[4];  const float* cbq = (const float*)d_in[5];
    const float* cwk = (const float*)d_in[6];  const float* cbk = (const float*)d_in[7];
    const float* cwv = (const float*)d_in[8];  const float* cbv = (const float*)d_in[9];
    const float* WQ = (const float*)d_in[10];
    const float* WK = (const float*)d_in[11];
    const float* WV = (const float*)d_in[12];
    const float* FC = (const float*)d_in[13];
    float* out = (float*)d_out;

    float *cq, *ck, *cv, *Q, *K, *V, *ctx, *fco, *attn_fb;
    cudaGetSymbolAddress((void**)&cq, g_cq);
    cudaGetSymbolAddress((void**)&ck, g_ck);
    cudaGetSymbolAddress((void**)&cv, g_cv);
    cudaGetSymbolAddress((void**)&Q,  g_Q);
    cudaGetSymbolAddress((void**)&K,  g_K);
    cudaGetSymbolAddress((void**)&V,  g_V);
    cudaGetSymbolAddress((void**)&ctx, g_ctx);
    cudaGetSymbolAddress((void**)&fco, g_fc);
    cudaGetSymbolAddress((void**)&attn_fb, g_attn_fb);

    const size_t BSD  = (size_t)BB * SS * DM;
    const size_t BHSS = (size_t)BH * SS * SS;
    float* attn = ((size_t)out_size >= BSD + BHSS) ? (out + BSD) : attn_fb;

    conv3x3_kernel<<<BB*SS, DM>>>(inQ, cwq, cbq, cq);
    conv3x3_kernel<<<BB*SS, DM>>>(inK, cwk, cbk, ck);
    conv3x3_kernel<<<BB*SS, DM>>>(inV, cwv, cbv, cv);

    dim3 gp(4, (BB*SS)/128);
    gemm512_tf32<<<gp, 256>>>(cq, WQ, Q);
    gemm512_tf32<<<gp, 256>>>(ck, WK, K);
    gemm512_tf32<<<gp, 256>>>(cv, WV, V);

    scores_tf32<<<dim3(8, 8, BH), 256>>>(Q, K, mask, attn);
    softmax_kernel<<<BH*SS, 128>>>(attn);
    context_tf32<<<dim3(8, BH), 256>>>(attn, V, ctx);

    gemm512_tf32<<<gp, 256>>>(ctx, FC, fco);
    ln_kernel<<<BB*SS, 128>>>(fco, inQ, out);
}